// round 12
// baseline (speedup 1.0000x reference)
#include <cuda_runtime.h>
#include <cuda_fp16.h>
#include <cstdint>
#include <math.h>

#define TT 16384
#define DD 256
#define HH 1024
#define EE 8
#define BM 64
#define HC 32
#define NCH (HH/HC)   // 32

// smem layout (bytes from dynamic base)
#define XS_OFF  0u                 // X: 64 x 512B, SWZ512
#define W1_OFF  32768u             // 2 x (32 rows x 512B, SWZ512)
#define W1_BUF  16384u
#define W2_OFF  65536u             // 2 x (256 rows x 64B, SWZ64)
#define W2_BUF  16384u
#define HS_OFF  98304u             // 2 x (64 rows x 64B, SWZ64)
#define HS_BUF  4096u
#define SMEM_BYTES 106496

// swizzles: 16B granules; conflict-free ldsm phases; 16B-aligned always
#define SWZ512(byte, row) ((byte) ^ (((row) & 7) << 4))
#define SWZ64(byte, row)  ((byte) ^ ((((row) >> 1) & 3) << 4))

__device__ int    g_counts[EE];
__device__ int    g_tok [EE*TT];
__device__ float  g_wt  [EE*TT];
__device__ int    g_slot[EE*TT];
__device__ float  g_contrib[2*TT*DD];
__device__ __half g_w1t[EE*HH*DD];   // [E][H][D]
__device__ __half g_w2t[EE*DD*HH];   // [E][D][H]

__device__ __forceinline__ uint32_t s2u(const void* p) {
    uint32_t a;
    asm("{ .reg .u64 t; cvta.to.shared.u64 t, %1; cvt.u32.u64 %0, t; }" : "=r"(a) : "l"(p));
    return a;
}
__device__ __forceinline__ void cpa16(uint32_t s, const void* g) {
    asm volatile("cp.async.cg.shared.global [%0], [%1], 16;" :: "r"(s), "l"(g));
}
#define CP_COMMIT() asm volatile("cp.async.commit_group;")
#define CP_WAIT0()  asm volatile("cp.async.wait_group 0;")

__device__ __forceinline__ void ldsm4(uint32_t& r0, uint32_t& r1, uint32_t& r2,
                                      uint32_t& r3, uint32_t a) {
    asm volatile("ldmatrix.sync.aligned.m8n8.x4.shared.b16 {%0,%1,%2,%3}, [%4];"
                 : "=r"(r0), "=r"(r1), "=r"(r2), "=r"(r3) : "r"(a));
}
__device__ __forceinline__ void mma16(float* c, const uint32_t* a,
                                      uint32_t b0, uint32_t b1) {
    asm volatile("mma.sync.aligned.m16n8k16.row.col.f32.f16.f16.f32 "
                 "{%0,%1,%2,%3}, {%4,%5,%6,%7}, {%8,%9}, {%0,%1,%2,%3};"
                 : "+f"(c[0]), "+f"(c[1]), "+f"(c[2]), "+f"(c[3])
                 : "r"(a[0]), "r"(a[1]), "r"(a[2]), "r"(a[3]), "r"(b0), "r"(b1));
}
__device__ __forceinline__ float gelu_f(float v) {
    float u = 0.7978845608f * fmaf(0.044715f * v, v * v, v);
    float t;
    asm("tanh.approx.f32 %0, %1;" : "=f"(t) : "f"(u));
    return 0.5f * v * (1.f + t);
}

// ---- fused transpose + fp16 convert for BOTH weights (blockIdx.z selects) --
__global__ __launch_bounds__(256) void transpose_kernel(
    const float* __restrict__ w1in, const float* __restrict__ w2in)
{
    __shared__ float tile[32][33];
    int which = blockIdx.z;
    const float* in = which ? w2in : w1in;
    __half* outp = which ? g_w2t : g_w1t;
    int M = which ? HH : DD;
    int N = which ? DD : HH;
    int ntj = N >> 5;
    int b = blockIdx.x, e = blockIdx.y;
    int ti = b / ntj, tj = b % ntj;
    const float* ine = in + (size_t)e * M * N;
    __half* oute = outp + (size_t)e * M * N;
    int c = threadIdx.x & 31, r8 = threadIdx.x >> 5;
#pragma unroll
    for (int it = 0; it < 4; it++) {
        int r = it * 8 + r8;
        tile[r][c] = __ldg(ine + (size_t)(ti*32 + r) * N + tj*32 + c);
    }
    __syncthreads();
#pragma unroll
    for (int it = 0; it < 4; it++) {
        int r = it * 8 + r8;
        oute[(size_t)(tj*32 + r) * M + ti*32 + c] = __float2half_rn(tile[c][r]);
    }
}

// ---------------- router: warp per token ------------------------------------
__global__ __launch_bounds__(256) void router_kernel(
    const float* __restrict__ x, const float* __restrict__ wr,
    const float* __restrict__ br, float* __restrict__ probs_out)
{
    int tid = threadIdx.x, lane = tid & 31;
    int t = (blockIdx.x * 256 + tid) >> 5;
    if (t >= TT) return;

    const float4* xr = (const float4*)(x + (size_t)t * DD + lane * 8);
    float4 x0 = __ldg(xr), x1 = __ldg(xr + 1);
    float xv[8] = {x0.x,x0.y,x0.z,x0.w,x1.x,x1.y,x1.z,x1.w};

    float l[EE];
#pragma unroll
    for (int e = 0; e < EE; e++) l[e] = 0.f;
    const float4* wrow = (const float4*)(wr + (size_t)(lane * 8) * EE);
#pragma unroll
    for (int j = 0; j < 8; j++) {
        float4 wa = __ldg(wrow + 2*j), wb = __ldg(wrow + 2*j + 1);
        l[0] = fmaf(xv[j], wa.x, l[0]); l[1] = fmaf(xv[j], wa.y, l[1]);
        l[2] = fmaf(xv[j], wa.z, l[2]); l[3] = fmaf(xv[j], wa.w, l[3]);
        l[4] = fmaf(xv[j], wb.x, l[4]); l[5] = fmaf(xv[j], wb.y, l[5]);
        l[6] = fmaf(xv[j], wb.z, l[6]); l[7] = fmaf(xv[j], wb.w, l[7]);
    }
#pragma unroll
    for (int off = 16; off > 0; off >>= 1)
#pragma unroll
        for (int e = 0; e < EE; e++) l[e] += __shfl_xor_sync(0xFFFFFFFF, l[e], off);

    if (lane) return;
#pragma unroll
    for (int e = 0; e < EE; e++) l[e] += __ldg(br + e);
    float mx = l[0];
#pragma unroll
    for (int e = 1; e < EE; e++) mx = fmaxf(mx, l[e]);
    float s = 0.f, p[EE];
#pragma unroll
    for (int e = 0; e < EE; e++) { p[e] = __expf(l[e] - mx); s += p[e]; }
    float inv = 1.f / s;
#pragma unroll
    for (int e = 0; e < EE; e++) p[e] *= inv;

    float4* po = (float4*)(probs_out + (size_t)t * EE);
    po[0] = make_float4(p[0],p[1],p[2],p[3]);
    po[1] = make_float4(p[4],p[5],p[6],p[7]);

    int i0 = 0; float v0 = p[0];
#pragma unroll
    for (int e = 1; e < EE; e++) if (p[e] > v0) { v0 = p[e]; i0 = e; }
    int i1 = -1; float v1 = -1.f;
#pragma unroll
    for (int e = 0; e < EE; e++) if (e != i0 && p[e] > v1) { v1 = p[e]; i1 = e; }
    float rs = 1.f / (v0 + v1);

    int p0 = atomicAdd(&g_counts[i0], 1);
    g_tok[i0*TT+p0] = t; g_wt[i0*TT+p0] = v0*rs; g_slot[i0*TT+p0] = 2*t;
    int p1 = atomicAdd(&g_counts[i1], 1);
    g_tok[i1*TT+p1] = t; g_wt[i1*TT+p1] = v1*rs; g_slot[i1*TT+p1] = 2*t+1;
}

// ---------------- FFN: fp16 mma.sync, chunk-pipelined (GEMM2|GEMM1) ---------
__global__ __launch_bounds__(256, 2) void ffn_kernel(
    const float* __restrict__ xg,
    const float* __restrict__ b1g, const float* __restrict__ b2g)
{
    extern __shared__ char sh[];
    __shared__ int toks[BM]; __shared__ float wts[BM]; __shared__ int slts[BM];

    int tid = threadIdx.x, wid = tid >> 5, lane = tid & 31;
    int qr = lane >> 2, qc = lane & 3;
    int wr = wid & 3, wc = wid >> 2;     // GEMM1: 4M x 2N (16x16 tile)
    int wr2 = wid & 1, wc2 = wid >> 1;   // GEMM2: 2M x 4N (32x64 tile)

    int e = -1, tile = 0, cnt = 0, acc = 0;
#pragma unroll
    for (int i = 0; i < EE; i++) {
        int c = g_counts[i], nt = (c + BM - 1) / BM;
        if (e < 0 && (int)blockIdx.x < acc + nt) { e = i; tile = blockIdx.x - acc; cnt = c; }
        acc += nt;
    }
    if (e < 0) return;
    int base = tile * BM, mval = min(BM, cnt - base);

    if (tid < BM) {
        if (tid < mval) {
            toks[tid] = g_tok [e*TT + base + tid];
            wts [tid] = g_wt  [e*TT + base + tid];
            slts[tid] = g_slot[e*TT + base + tid];
        } else { toks[tid] = 0; wts[tid] = 0.f; slts[tid] = 0; }
    }
    __syncthreads();

    const __half* w1te = g_w1t + (size_t)e * HH * DD;   // [H][D]
    const __half* w2te = g_w2t + (size_t)e * DD * HH;   // [D][H]
    const float*  b1e  = b1g + (size_t)e * HH;
    const float*  b2e  = b2g + (size_t)e * DD;

    uint32_t smb = s2u(sh);
    uint32_t xs_b = smb + XS_OFF;

    int a_row = lane & 15, a_kof = 8 * (lane >> 4);
    int b_row = ((lane >> 4) << 3) + (lane & 7);
    int b_kof = 8 * ((lane >> 3) & 1);

    // W1 chunk: 32 rows x 512B = 1024 x 16B segments -> i < 4  (FIXED)
#define LD_W1(bufsel, chunk) do {                                              \
    uint32_t dst = smb + W1_OFF + (bufsel)*W1_BUF;                             \
    const __half* src = w1te + (size_t)(chunk)*HC*DD;                          \
    _Pragma("unroll")                                                          \
    for (int i = 0; i < 4; i++) {                                              \
        int f = tid + i*256, row = f >> 5, seg = f & 31;                       \
        cpa16(dst + (uint32_t)(row*512 + SWZ512(seg*16, row)),                 \
              src + (size_t)row*DD + seg*8);                                   \
    } } while(0)
    // W2 chunk: 256 rows x 64B, SWZ64
#define LD_W2(bufsel, chunk) do {                                              \
    uint32_t dst = smb + W2_OFF + (bufsel)*W2_BUF;                             \
    const __half* src = w2te + (size_t)(chunk)*HC;                             \
    _Pragma("unroll")                                                          \
    for (int i = 0; i < 4; i++) {                                              \
        int f = tid + i*256, row = f >> 2, seg = f & 3;                        \
        cpa16(dst + (uint32_t)(row*64 + SWZ64(seg*16, row)),                   \
              src + (size_t)row*HH + seg*8);                                   \
    } } while(0)
    // GEMM1: c1[2][4] = X[rows wr*16..] @ W1buf[cols wc*16..], K=256
#define GEMM1(bufsel, c1) do {                                                 \
    uint32_t w1b = smb + W1_OFF + (bufsel)*W1_BUF;                             \
    _Pragma("unroll")                                                          \
    for (int ks = 0; ks < 16; ks++) {                                          \
        int k0 = ks * 16;                                                      \
        uint32_t a_[4], b_[4];                                                 \
        { int row = wr*16 + a_row;                                             \
          ldsm4(a_[0],a_[1],a_[2],a_[3],                                       \
                xs_b + (uint32_t)(row*512 + SWZ512((k0 + a_kof)*2, row))); }   \
        { int row = wc*16 + b_row;                                             \
          ldsm4(b_[0],b_[1],b_[2],b_[3],                                       \
                w1b + (uint32_t)(row*512 + SWZ512((k0 + b_kof)*2, row))); }    \
        mma16((c1)[0], a_, b_[0], b_[1]);                                      \
        mma16((c1)[1], a_, b_[2], b_[3]);                                      \
    } } while(0)
    // GELU + store to Hs buffer (64B rows, SWZ64)
#define GELU_ST(bufsel, c1, chunk) do {                                        \
    uint32_t hof = HS_OFF + (bufsel)*HS_BUF;                                   \
    _Pragma("unroll")                                                          \
    for (int nt = 0; nt < 2; nt++) {                                           \
        int col = wc*16 + nt*8 + 2*qc;                                         \
        float bb0 = __ldg(b1e + (chunk)*HC + col);                             \
        float bb1 = __ldg(b1e + (chunk)*HC + col + 1);                         \
        int r = wr*16 + qr;                                                    \
        float v0 = gelu_f((c1)[nt][0] + bb0), v1 = gelu_f((c1)[nt][1] + bb1);  \
        float v2 = gelu_f((c1)[nt][2] + bb0), v3 = gelu_f((c1)[nt][3] + bb1);  \
        *reinterpret_cast<__half2*>(sh + hof + r*64 + SWZ64(col*2, r))         \
            = __floats2half2_rn(v0, v1);                                       \
        *reinterpret_cast<__half2*>(sh + hof + (r+8)*64 + SWZ64(col*2, r+8))   \
            = __floats2half2_rn(v2, v3);                                       \
    } } while(0)
    // GEMM2: c2 += Hs[rows wr2*32..] @ W2buf[cols wc2*64..], K=32
#define GEMM2(bufsel, c2) do {                                                 \
    uint32_t hsb = smb + HS_OFF + (bufsel)*HS_BUF;                             \
    uint32_t w2b = smb + W2_OFF + (bufsel)*W2_BUF;                             \
    _Pragma("unroll")                                                          \
    for (int ks = 0; ks < 2; ks++) {                                           \
        int k0 = ks * 16;                                                      \
        uint32_t a0_[4], a1_[4];                                               \
        { int row = wr2*32 + a_row;                                            \
          ldsm4(a0_[0],a0_[1],a0_[2],a0_[3],                                   \
                hsb + (uint32_t)(row*64 + SWZ64((k0 + a_kof)*2, row))); }      \
        { int row = wr2*32 + 16 + a_row;                                       \
          ldsm4(a1_[0],a1_[1],a1_[2],a1_[3],                                   \
                hsb + (uint32_t)(row*64 + SWZ64((k0 + a_kof)*2, row))); }      \
        _Pragma("unroll")                                                      \
        for (int p = 0; p < 4; p++) {                                          \
            uint32_t b_[4];                                                    \
            int row = wc2*64 + p*16 + b_row;                                   \
            ldsm4(b_[0],b_[1],b_[2],b_[3],                                     \
                  w2b + (uint32_t)(row*64 + SWZ64((k0 + b_kof)*2, row)));      \
            mma16((c2)[0][2*p],   a0_, b_[0], b_[1]);                          \
            mma16((c2)[0][2*p+1], a0_, b_[2], b_[3]);                          \
            mma16((c2)[1][2*p],   a1_, b_[0], b_[1]);                          \
            mma16((c2)[1][2*p+1], a1_, b_[2], b_[3]);                          \
        }                                                                      \
    } } while(0)

    // ---- prologue ----
    LD_W1(0, 0);
    CP_COMMIT();
    for (int i4 = tid; i4 < BM*64; i4 += 256) {
        int r = i4 >> 6, c4 = i4 & 63;
        float4 v = (r < mval) ? __ldg((const float4*)(xg + (size_t)toks[r]*DD + c4*4))
                              : make_float4(0.f,0.f,0.f,0.f);
        __half2 h0 = __floats2half2_rn(v.x, v.y);
        __half2 h1 = __floats2half2_rn(v.z, v.w);
        uint2 u;
        u.x = *reinterpret_cast<uint32_t*>(&h0);
        u.y = *reinterpret_cast<uint32_t*>(&h1);
        *reinterpret_cast<uint2*>(sh + XS_OFF + r*512 + SWZ512(c4*8, r)) = u;
    }
    CP_WAIT0();
    __syncthreads();       // X + W1(0) ready

    LD_W2(0, 0);
    LD_W1(1, 1);
    CP_COMMIT();
    {
        float c1[2][4];
#pragma unroll
        for (int nt = 0; nt < 2; nt++)
#pragma unroll
            for (int c = 0; c < 4; c++) c1[nt][c] = 0.f;
        GEMM1(0, c1);
        GELU_ST(0, c1, 0);
    }
    CP_WAIT0();
    __syncthreads();       // Hs(0), W2(0), W1(1) ready

    float c2[2][8][4];
#pragma unroll
    for (int mt = 0; mt < 2; mt++)
#pragma unroll
        for (int nt = 0; nt < 8; nt++)
#pragma unroll
            for (int c = 0; c < 4; c++) c2[mt][nt][c] = 0.f;

    // ---- main pipelined loop: GEMM2(hc) || GEMM1(hc+1) in one block ----
#pragma unroll 1
    for (int hc = 0; hc < NCH - 1; hc++) {
        int cb = hc & 1, nb = cb ^ 1;
        if (hc + 2 < NCH) LD_W1(cb, hc + 2);
        LD_W2(nb, hc + 1);
        CP_COMMIT();

        float c1[2][4];
#pragma unroll
        for (int nt = 0; nt < 2; nt++)
#pragma unroll
            for (int c = 0; c < 4; c++) c1[nt][c] = 0.f;

        GEMM2(cb, c2);        // independent chain 1
        GEMM1(nb, c1);        // independent chain 2
        GELU_ST(nb, c1, hc + 1);

        CP_WAIT0();
        __syncthreads();
    }
    GEMM2((NCH - 1) & 1, c2); // last chunk

    // ---- epilogue: contrib[slot] = w * (y + b2) ----
#pragma unroll
    for (int mt = 0; mt < 2; mt++)
#pragma unroll
        for (int half = 0; half < 2; half++) {
            int r = wr2*32 + mt*16 + qr + half*8;
            if (r < mval) {
                float w = wts[r];
                float* crow = g_contrib + (size_t)slts[r] * DD;
#pragma unroll
                for (int nt = 0; nt < 8; nt++) {
                    int col = wc2*64 + nt*8 + 2*qc;
                    float2 o;
                    o.x = w * (c2[mt][nt][half*2+0] + __ldg(b2e + col));
                    o.y = w * (c2[mt][nt][half*2+1] + __ldg(b2e + col + 1));
                    *(float2*)(crow + col) = o;
                }
            }
        }
}

// ---------------- combine + counter reset -----------------------------------
__global__ __launch_bounds__(256) void combine_kernel(float* __restrict__ out)
{
    int g = blockIdx.x * 256 + threadIdx.x;
    int t = g >> 6, q = g & 63;
    const float4* c4 = (const float4*)g_contrib;
    float4 a = c4[(size_t)(2*t) * 64 + q];
    float4 b = c4[(size_t)(2*t+1) * 64 + q];
    ((float4*)out)[g] = make_float4(a.x+b.x, a.y+b.y, a.z+b.z, a.w+b.w);
    if (g < EE) g_counts[g] = 0;
}

extern "C" void kernel_launch(void* const* d_in, const int* in_sizes, int n_in,
                              void* d_out, int out_size)
{
    const float* x  = (const float*)d_in[0];
    const float* wr = (const float*)d_in[1];
    const float* br = (const float*)d_in[2];
    const float* w1 = (const float*)d_in[3];
    const float* b1 = (const float*)d_in[4];
    const float* w2 = (const float*)d_in[5];
    const float* b2 = (const float*)d_in[6];
    float* out = (float*)d_out;
    float* probs_out = out + (size_t)TT * DD;

    transpose_kernel<<<dim3(256, EE, 2), 256>>>(w1, w2);
    router_kernel<<<TT/8, 256>>>(x, wr, br, probs_out);

    cudaFuncSetAttribute(ffn_kernel, cudaFuncAttributeMaxDynamicSharedMemorySize, SMEM_BYTES);
    ffn_kernel<<<(2*TT)/BM + EE, 256, SMEM_BYTES>>>(x, b1, b2);

    combine_kernel<<<(TT*DD/4)/256, 256>>>(out);
}

// round 13
// speedup vs baseline: 1.0736x; 1.0736x over previous
#include <cuda_runtime.h>
#include <cuda_fp16.h>
#include <cstdint>
#include <math.h>

#define TT 16384
#define DD 256
#define HH 1024
#define EE 8
#define BM 64
#define HC 64
#define NCH (HH/HC)   // 16

// smem byte offsets (dynamic smem base) — round-9 layout (190.6us baseline)
#define XS_OFF  0u        // X:  64 rows x 512B, SWZ512
#define W1_OFF  32768u    // W1c: 64 rows x 512B, SWZ512   [n][k=256]
#define W2_OFF  65536u    // W2c: 256 rows x 144B (stride 72 halves) [n][k=64]
#define HS_OFF  102400u   // Hs: 64 rows x 144B
#define W2_S 72
#define HS_S 72
#define SMEM_BYTES 111616

#define SWZ512(byte, row) ((byte) ^ (((row) & 7) << 4))

__device__ int    g_counts[EE];
__device__ int    g_tok [EE*TT];
__device__ float  g_wt  [EE*TT];
__device__ int    g_slot[EE*TT];
__device__ float  g_contrib[2*TT*DD];
__device__ __half g_w1t[EE*HH*DD];   // [E][H][D] fp16
__device__ __half g_w2t[EE*DD*HH];   // [E][D][H] fp16

__device__ __forceinline__ uint32_t s2u(const void* p) {
    uint32_t a;
    asm("{ .reg .u64 t; cvta.to.shared.u64 t, %1; cvt.u32.u64 %0, t; }" : "=r"(a) : "l"(p));
    return a;
}
__device__ __forceinline__ void cpa16(uint32_t s, const void* g) {
    asm volatile("cp.async.cg.shared.global [%0], [%1], 16;" :: "r"(s), "l"(g));
}
#define CP_COMMIT() asm volatile("cp.async.commit_group;")
#define CP_WAIT0()  asm volatile("cp.async.wait_group 0;")

__device__ __forceinline__ void ldsm4(uint32_t& r0, uint32_t& r1, uint32_t& r2,
                                      uint32_t& r3, uint32_t a) {
    asm volatile("ldmatrix.sync.aligned.m8n8.x4.shared.b16 {%0,%1,%2,%3}, [%4];"
                 : "=r"(r0), "=r"(r1), "=r"(r2), "=r"(r3) : "r"(a));
}
// NOTE: non-volatile — pure register op, lets the compiler sink mma past ldsm
__device__ __forceinline__ void mma16(float* c, const uint32_t* a,
                                      uint32_t b0, uint32_t b1) {
    asm("mma.sync.aligned.m16n8k16.row.col.f32.f16.f16.f32 "
        "{%0,%1,%2,%3}, {%4,%5,%6,%7}, {%8,%9}, {%0,%1,%2,%3};"
        : "+f"(c[0]), "+f"(c[1]), "+f"(c[2]), "+f"(c[3])
        : "r"(a[0]), "r"(a[1]), "r"(a[2]), "r"(a[3]), "r"(b0), "r"(b1));
}
__device__ __forceinline__ float gelu_f(float v) {
    float u = 0.7978845608f * fmaf(0.044715f * v, v * v, v);
    float t;
    asm("tanh.approx.f32 %0, %1;" : "=f"(t) : "f"(u));
    return 0.5f * v * (1.f + t);
}

// ---- fused prep: weight transpose+cvt (blocks 0..4095) + router (4096..6143)
__global__ __launch_bounds__(256) void prep_kernel(
    const float* __restrict__ w1in, const float* __restrict__ w2in,
    const float* __restrict__ x,    const float* __restrict__ wrr,
    const float* __restrict__ br,   float* __restrict__ probs_out)
{
    __shared__ float tile[32][33];
    int bid = blockIdx.x;
    int tid = threadIdx.x;

    if (bid < 4096) {
        int which = bid >> 11;          // 0: w1 (256x1024), 1: w2 (1024x256)
        int rem = bid & 2047;
        int e = rem >> 8, b = rem & 255;
        const float* in = which ? w2in : w1in;
        __half* outp = which ? g_w2t : g_w1t;
        int M = which ? HH : DD;
        int N = which ? DD : HH;
        int ntj = N >> 5;
        int ti = b / ntj, tj = b % ntj;
        const float* ine = in + (size_t)e * M * N;
        __half* oute = outp + (size_t)e * M * N;
        int c = tid & 31, r8 = tid >> 5;
#pragma unroll
        for (int it = 0; it < 4; it++) {
            int r = it * 8 + r8;
            tile[r][c] = __ldg(ine + (size_t)(ti*32 + r) * N + tj*32 + c);
        }
        __syncthreads();
#pragma unroll
        for (int it = 0; it < 4; it++) {
            int r = it * 8 + r8;
            oute[(size_t)(tj*32 + r) * M + ti*32 + c] = __float2half_rn(tile[c][r]);
        }
        return;
    }

    // ---- router: warp per token ----
    int lane = tid & 31;
    int t = ((bid - 4096) * 256 + tid) >> 5;
    if (t >= TT) return;

    const float4* xr = (const float4*)(x + (size_t)t * DD + lane * 8);
    float4 x0 = __ldg(xr), x1 = __ldg(xr + 1);
    float xv[8] = {x0.x,x0.y,x0.z,x0.w,x1.x,x1.y,x1.z,x1.w};

    float l[EE];
#pragma unroll
    for (int e = 0; e < EE; e++) l[e] = 0.f;
    const float4* wrow = (const float4*)(wrr + (size_t)(lane * 8) * EE);
#pragma unroll
    for (int j = 0; j < 8; j++) {
        float4 wa = __ldg(wrow + 2*j), wb = __ldg(wrow + 2*j + 1);
        l[0] = fmaf(xv[j], wa.x, l[0]); l[1] = fmaf(xv[j], wa.y, l[1]);
        l[2] = fmaf(xv[j], wa.z, l[2]); l[3] = fmaf(xv[j], wa.w, l[3]);
        l[4] = fmaf(xv[j], wb.x, l[4]); l[5] = fmaf(xv[j], wb.y, l[5]);
        l[6] = fmaf(xv[j], wb.z, l[6]); l[7] = fmaf(xv[j], wb.w, l[7]);
    }
#pragma unroll
    for (int off = 16; off > 0; off >>= 1)
#pragma unroll
        for (int e = 0; e < EE; e++) l[e] += __shfl_xor_sync(0xFFFFFFFF, l[e], off);

    if (lane) return;
#pragma unroll
    for (int e = 0; e < EE; e++) l[e] += __ldg(br + e);
    float mx = l[0];
#pragma unroll
    for (int e = 1; e < EE; e++) mx = fmaxf(mx, l[e]);
    float s = 0.f, p[EE];
#pragma unroll
    for (int e = 0; e < EE; e++) { p[e] = __expf(l[e] - mx); s += p[e]; }
    float inv = 1.f / s;
#pragma unroll
    for (int e = 0; e < EE; e++) p[e] *= inv;

    float4* po = (float4*)(probs_out + (size_t)t * EE);
    po[0] = make_float4(p[0],p[1],p[2],p[3]);
    po[1] = make_float4(p[4],p[5],p[6],p[7]);

    int i0 = 0; float v0 = p[0];
#pragma unroll
    for (int e = 1; e < EE; e++) if (p[e] > v0) { v0 = p[e]; i0 = e; }
    int i1 = -1; float v1 = -1.f;
#pragma unroll
    for (int e = 0; e < EE; e++) if (e != i0 && p[e] > v1) { v1 = p[e]; i1 = e; }
    float rs = 1.f / (v0 + v1);

    int p0 = atomicAdd(&g_counts[i0], 1);
    g_tok[i0*TT+p0] = t; g_wt[i0*TT+p0] = v0*rs; g_slot[i0*TT+p0] = 2*t;
    int p1 = atomicAdd(&g_counts[i1], 1);
    g_tok[i1*TT+p1] = t; g_wt[i1*TT+p1] = v1*rs; g_slot[i1*TT+p1] = 2*t+1;
}

// ---------------- FFN: fp16 mma.sync, HC=64, reg-pipelined GEMM1 ------------
__global__ __launch_bounds__(256, 2) void ffn_kernel(
    const float* __restrict__ xg,
    const float* __restrict__ b1g, const float* __restrict__ b2g)
{
    extern __shared__ char sh[];
    __shared__ int toks[BM]; __shared__ float wts[BM]; __shared__ int slts[BM];

    int tid = threadIdx.x, wid = tid >> 5, lane = tid & 31;
    int qr = lane >> 2, qc = lane & 3;
    int wr = wid & 3, wc = wid >> 2;     // GEMM1: 4M x 2N (16x32 tile)
    int wr2 = wid & 1, wc2 = wid >> 1;   // GEMM2: 2M x 4N (32x64 tile)

    int e = -1, tile = 0, cnt = 0, acc = 0;
#pragma unroll
    for (int i = 0; i < EE; i++) {
        int c = g_counts[i], nt = (c + BM - 1) / BM;
        if (e < 0 && (int)blockIdx.x < acc + nt) { e = i; tile = blockIdx.x - acc; cnt = c; }
        acc += nt;
    }
    if (e < 0) return;
    int base = tile * BM, mval = min(BM, cnt - base);

    if (tid < BM) {
        if (tid < mval) {
            toks[tid] = g_tok [e*TT + base + tid];
            wts [tid] = g_wt  [e*TT + base + tid];
            slts[tid] = g_slot[e*TT + base + tid];
        } else { toks[tid] = 0; wts[tid] = 0.f; slts[tid] = 0; }
    }
    __syncthreads();

    const __half* w1te = g_w1t + (size_t)e * HH * DD;   // [H][D]
    const __half* w2te = g_w2t + (size_t)e * DD * HH;   // [D][H]
    const float*  b1e  = b1g + (size_t)e * HH;
    const float*  b2e  = b2g + (size_t)e * DD;

    uint32_t smb = s2u(sh);
    uint32_t xs_b = smb + XS_OFF, w1_b = smb + W1_OFF;
    uint32_t w2_b = smb + W2_OFF, hs_b = smb + HS_OFF;

    int a_row = lane & 15, a_kof = 8 * (lane >> 4);
    int b_row = ((lane >> 4) << 3) + (lane & 7);
    int b_kof = 8 * ((lane >> 3) & 1);

    // prologue: W1 chunk 0 (64 rows x 512B, swizzled)
#pragma unroll
    for (int i = 0; i < 8; i++) {
        int f = tid + i*256, row = f >> 5, seg = f & 31;
        cpa16(w1_b + (uint32_t)(row*512 + SWZ512(seg*16, row)),
              w1te + (size_t)row*DD + seg*8);
    }
    CP_COMMIT();
    for (int i4 = tid; i4 < BM*64; i4 += 256) {
        int r = i4 >> 6, c4 = i4 & 63;
        float4 v = (r < mval) ? __ldg((const float4*)(xg + (size_t)toks[r]*DD + c4*4))
                              : make_float4(0.f,0.f,0.f,0.f);
        __half2 h0 = __floats2half2_rn(v.x, v.y);
        __half2 h1 = __floats2half2_rn(v.z, v.w);
        uint2 u;
        u.x = *reinterpret_cast<uint32_t*>(&h0);
        u.y = *reinterpret_cast<uint32_t*>(&h1);
        *reinterpret_cast<uint2*>(sh + XS_OFF + r*512 + SWZ512(c4*8, r)) = u;
    }
    CP_WAIT0();
    __syncthreads();

    float c2[2][8][4];
#pragma unroll
    for (int mt = 0; mt < 2; mt++)
#pragma unroll
        for (int nt = 0; nt < 8; nt++)
#pragma unroll
            for (int c = 0; c < 4; c++) c2[mt][nt][c] = 0.f;

#pragma unroll 1
    for (int hc = 0; hc < NCH; hc++) {
        // prefetch W2 chunk hc (256 rows x 128B, stride 144B)
#pragma unroll
        for (int i = 0; i < 8; i++) {
            int f = tid + i*256, row = f >> 3, seg = f & 7;
            cpa16(w2_b + (uint32_t)(row*(W2_S*2) + seg*16),
                  w2te + (size_t)row*HH + hc*HC + seg*8);
        }
        CP_COMMIT();

        // ---- GEMM1 (register-pipelined): C1[64,64] = X @ W1c ; tile 16x32
        float c1[4][4];
#pragma unroll
        for (int nt = 0; nt < 4; nt++)
#pragma unroll
            for (int c = 0; c < 4; c++) c1[nt][c] = 0.f;

        {
            uint32_t af[2][4], b0f[2][4], b1f[2][4];
            {   // preload ks=0
                int row = wr*16 + a_row;
                ldsm4(af[0][0],af[0][1],af[0][2],af[0][3],
                      xs_b + (uint32_t)(row*512 + SWZ512((a_kof)*2, row)));
                row = wc*32 + b_row;
                ldsm4(b0f[0][0],b0f[0][1],b0f[0][2],b0f[0][3],
                      w1_b + (uint32_t)(row*512 + SWZ512((b_kof)*2, row)));
                row += 16;
                ldsm4(b1f[0][0],b1f[0][1],b1f[0][2],b1f[0][3],
                      w1_b + (uint32_t)(row*512 + SWZ512((b_kof)*2, row)));
            }
#pragma unroll
            for (int ks = 0; ks < 16; ks++) {
                int cur = ks & 1, nxt = cur ^ 1;
                if (ks < 15) {
                    int k0 = (ks + 1) * 16;
                    int row = wr*16 + a_row;
                    ldsm4(af[nxt][0],af[nxt][1],af[nxt][2],af[nxt][3],
                          xs_b + (uint32_t)(row*512 + SWZ512((k0 + a_kof)*2, row)));
                    row = wc*32 + b_row;
                    ldsm4(b0f[nxt][0],b0f[nxt][1],b0f[nxt][2],b0f[nxt][3],
                          w1_b + (uint32_t)(row*512 + SWZ512((k0 + b_kof)*2, row)));
                    row += 16;
                    ldsm4(b1f[nxt][0],b1f[nxt][1],b1f[nxt][2],b1f[nxt][3],
                          w1_b + (uint32_t)(row*512 + SWZ512((k0 + b_kof)*2, row)));
                }
                mma16(c1[0], af[cur], b0f[cur][0], b0f[cur][1]);
                mma16(c1[1], af[cur], b0f[cur][2], b0f[cur][3]);
                mma16(c1[2], af[cur], b1f[cur][0], b1f[cur][1]);
                mma16(c1[3], af[cur], b1f[cur][2], b1f[cur][3]);
            }
        }

        // ---- bias + fast GELU -> Hs (W2 cp.async still in flight)
#pragma unroll
        for (int nt = 0; nt < 4; nt++) {
            int col = wc*32 + nt*8 + 2*qc;
            float bb0 = __ldg(b1e + hc*HC + col);
            float bb1 = __ldg(b1e + hc*HC + col + 1);
            int r = wr*16 + qr;
            float v0 = gelu_f(c1[nt][0] + bb0), v1 = gelu_f(c1[nt][1] + bb1);
            float v2 = gelu_f(c1[nt][2] + bb0), v3 = gelu_f(c1[nt][3] + bb1);
            *reinterpret_cast<__half2*>(sh + HS_OFF + (r*HS_S + col)*2)
                = __floats2half2_rn(v0, v1);
            *reinterpret_cast<__half2*>(sh + HS_OFF + ((r+8)*HS_S + col)*2)
                = __floats2half2_rn(v2, v3);
        }
        CP_WAIT0();        // W2 chunk ready
        __syncthreads();   // Hs + W2 visible

        // prefetch W1 chunk hc+1 (overlaps GEMM2)
        if (hc + 1 < NCH) {
#pragma unroll
            for (int i = 0; i < 8; i++) {
                int f = tid + i*256, row = f >> 5, seg = f & 31;
                cpa16(w1_b + (uint32_t)(row*512 + SWZ512(seg*16, row)),
                      w1te + (size_t)((hc+1)*HC + row)*DD + seg*8);
            }
        }
        CP_COMMIT();

        // ---- GEMM2: C2[64,256] += H[64,64] @ W2c ; warp tile 32x64
#pragma unroll
        for (int ks = 0; ks < 4; ks++) {
            int k0 = ks * 16;
            uint32_t a0[4], a1[4];
            ldsm4(a0[0],a0[1],a0[2],a0[3],
                  hs_b + (uint32_t)(((wr2*32 + a_row)*HS_S + k0 + a_kof) * 2));
            ldsm4(a1[0],a1[1],a1[2],a1[3],
                  hs_b + (uint32_t)(((wr2*32 + 16 + a_row)*HS_S + k0 + a_kof) * 2));
#pragma unroll
            for (int p = 0; p < 4; p++) {
                uint32_t b[4];
                ldsm4(b[0],b[1],b[2],b[3],
                      w2_b + (uint32_t)(((wc2*64 + p*16 + b_row)*W2_S + k0 + b_kof) * 2));
                mma16(c2[0][2*p],   a0, b[0], b[1]);
                mma16(c2[0][2*p+1], a0, b[2], b[3]);
                mma16(c2[1][2*p],   a1, b[0], b[1]);
                mma16(c2[1][2*p+1], a1, b[2], b[3]);
            }
        }
        CP_WAIT0();    // W1 next ready
        __syncthreads();
    }

    // ---- epilogue: contrib[slot] = w * (y + b2)
#pragma unroll
    for (int mt = 0; mt < 2; mt++)
#pragma unroll
        for (int half = 0; half < 2; half++) {
            int r = wr2*32 + mt*16 + qr + half*8;
            if (r < mval) {
                float w = wts[r];
                float* crow = g_contrib + (size_t)slts[r] * DD;
#pragma unroll
                for (int nt = 0; nt < 8; nt++) {
                    int col = wc2*64 + nt*8 + 2*qc;
                    float2 o;
                    o.x = w * (c2[mt][nt][half*2+0] + __ldg(b2e + col));
                    o.y = w * (c2[mt][nt][half*2+1] + __ldg(b2e + col + 1));
                    *(float2*)(crow + col) = o;
                }
            }
        }
}

// ---------------- combine + counter reset -----------------------------------
__global__ __launch_bounds__(256) void combine_kernel(float* __restrict__ out)
{
    int g = blockIdx.x * 256 + threadIdx.x;
    int t = g >> 6, q = g & 63;
    const float4* c4 = (const float4*)g_contrib;
    float4 a = c4[(size_t)(2*t) * 64 + q];
    float4 b = c4[(size_t)(2*t+1) * 64 + q];
    ((float4*)out)[g] = make_float4(a.x+b.x, a.y+b.y, a.z+b.z, a.w+b.w);
    if (g < EE) g_counts[g] = 0;
}

extern "C" void kernel_launch(void* const* d_in, const int* in_sizes, int n_in,
                              void* d_out, int out_size)
{
    const float* x  = (const float*)d_in[0];
    const float* wr = (const float*)d_in[1];
    const float* br = (const float*)d_in[2];
    const float* w1 = (const float*)d_in[3];
    const float* b1 = (const float*)d_in[4];
    const float* w2 = (const float*)d_in[5];
    const float* b2 = (const float*)d_in[6];
    float* out = (float*)d_out;
    float* probs_out = out + (size_t)TT * DD;

    prep_kernel<<<6144, 256>>>(w1, w2, x, wr, br, probs_out);

    cudaFuncSetAttribute(ffn_kernel, cudaFuncAttributeMaxDynamicSharedMemorySize, SMEM_BYTES);
    ffn_kernel<<<(2*TT)/BM + EE, 256, SMEM_BYTES>>>(x, b1, b2);

    combine_kernel<<<(TT*DD/4)/256, 256>>>(out);
}

// round 14
// speedup vs baseline: 1.1254x; 1.0482x over previous
#include <cuda_runtime.h>
#include <cuda_fp16.h>
#include <cstdint>
#include <math.h>

#define TT 16384
#define DD 256
#define HH 1024
#define EE 8
#define BM 64
#define HC 64
#define NCH (HH/HC)   // 16

// smem byte offsets (dynamic smem base)
#define XS_OFF  0u        // X:  64 rows x 512B, SWZ512
#define W1_OFF  32768u    // W1c: 64 rows x 512B, SWZ512   [n][k=256]
#define W2_OFF  65536u    // W2c: 256 rows x 144B (stride 72 halves) [n][k=64]
#define HS_OFF  102400u   // Hs: 64 rows x 144B
#define W2_S 72
#define HS_S 72
#define SMEM_BYTES 111616

#define SWZ512(byte, row) ((byte) ^ (((row) & 7) << 4))

__device__ int    g_counts[EE];
__device__ int    g_tok [EE*TT];
__device__ float  g_wt  [EE*TT];
__device__ int    g_slot[EE*TT];
__device__ float  g_contrib[2*TT*DD];
__device__ __half g_w1t[EE*HH*DD];   // [E][H][D] fp16
__device__ __half g_w2t[EE*DD*HH];   // [E][D][H] fp16

__device__ __forceinline__ uint32_t s2u(const void* p) {
    uint32_t a;
    asm("{ .reg .u64 t; cvta.to.shared.u64 t, %1; cvt.u32.u64 %0, t; }" : "=r"(a) : "l"(p));
    return a;
}
__device__ __forceinline__ void cpa16(uint32_t s, const void* g) {
    asm volatile("cp.async.cg.shared.global [%0], [%1], 16;" :: "r"(s), "l"(g));
}
#define CP_COMMIT() asm volatile("cp.async.commit_group;")
#define CP_WAIT0()  asm volatile("cp.async.wait_group 0;")

__device__ __forceinline__ void ldsm4(uint32_t& r0, uint32_t& r1, uint32_t& r2,
                                      uint32_t& r3, uint32_t a) {
    asm volatile("ldmatrix.sync.aligned.m8n8.x4.shared.b16 {%0,%1,%2,%3}, [%4];"
                 : "=r"(r0), "=r"(r1), "=r"(r2), "=r"(r3) : "r"(a));
}
__device__ __forceinline__ void mma16(float* c, const uint32_t* a,
                                      uint32_t b0, uint32_t b1) {
    asm("mma.sync.aligned.m16n8k16.row.col.f32.f16.f16.f32 "
        "{%0,%1,%2,%3}, {%4,%5,%6,%7}, {%8,%9}, {%0,%1,%2,%3};"
        : "+f"(c[0]), "+f"(c[1]), "+f"(c[2]), "+f"(c[3])
        : "r"(a[0]), "r"(a[1]), "r"(a[2]), "r"(a[3]), "r"(b0), "r"(b1));
}
__device__ __forceinline__ float gelu_f(float v) {
    float u = 0.7978845608f * fmaf(0.044715f * v, v * v, v);
    float t;
    asm("tanh.approx.f32 %0, %1;" : "=f"(t) : "f"(u));
    return 0.5f * v * (1.f + t);
}

// ---- fused prep: weight transpose+cvt (blocks 0..4095) + router (4096..6143)
__global__ __launch_bounds__(256) void prep_kernel(
    const float* __restrict__ w1in, const float* __restrict__ w2in,
    const float* __restrict__ x,    const float* __restrict__ wrr,
    const float* __restrict__ br,   float* __restrict__ probs_out)
{
    __shared__ float tile[32][33];
    __shared__ float4 wsm[544];       // 512 float4 + 1 pad per 16 (conflict-free)
    int bid = blockIdx.x;
    int tid = threadIdx.x;

    if (bid < 4096) {
        int which = bid >> 11;          // 0: w1 (256x1024), 1: w2 (1024x256)
        int rem = bid & 2047;
        int e = rem >> 8, b = rem & 255;
        const float* in = which ? w2in : w1in;
        __half* outp = which ? g_w2t : g_w1t;
        int M = which ? HH : DD;
        int N = which ? DD : HH;
        int ntj = N >> 5;
        int ti = b / ntj, tj = b % ntj;
        const float* ine = in + (size_t)e * M * N;
        __half* oute = outp + (size_t)e * M * N;
        int c = tid & 31, r8 = tid >> 5;
#pragma unroll
        for (int it = 0; it < 4; it++) {
            int r = it * 8 + r8;
            tile[r][c] = __ldg(ine + (size_t)(ti*32 + r) * N + tj*32 + c);
        }
        __syncthreads();
#pragma unroll
        for (int it = 0; it < 4; it++) {
            int r = it * 8 + r8;
            oute[(size_t)(tj*32 + r) * M + ti*32 + c] = __float2half_rn(tile[c][r]);
        }
        return;
    }

    // ---- router: warp per token, w_router staged in padded smem ----
    // stage: logical float4 i -> phys i + i/16, coalesced global read
#pragma unroll
    for (int i = tid; i < 512; i += 256)
        wsm[i + (i >> 4)] = __ldg(((const float4*)wrr) + i);
    __syncthreads();

    int lane = tid & 31;
    int t = ((bid - 4096) * 256 + tid) >> 5;
    if (t >= TT) return;

    const float4* xr = (const float4*)(x + (size_t)t * DD + lane * 8);
    float4 x0 = __ldg(xr), x1 = __ldg(xr + 1);
    float xv[8] = {x0.x,x0.y,x0.z,x0.w,x1.x,x1.y,x1.z,x1.w};

    float l[EE];
#pragma unroll
    for (int e = 0; e < EE; e++) l[e] = 0.f;
    // lane's w slice: logical float4 idx lane*16 + k -> phys lane*17 + k
    const float4* wl = wsm + lane * 17;
#pragma unroll
    for (int j = 0; j < 8; j++) {
        float4 wa = wl[2*j], wb = wl[2*j + 1];
        l[0] = fmaf(xv[j], wa.x, l[0]); l[1] = fmaf(xv[j], wa.y, l[1]);
        l[2] = fmaf(xv[j], wa.z, l[2]); l[3] = fmaf(xv[j], wa.w, l[3]);
        l[4] = fmaf(xv[j], wb.x, l[4]); l[5] = fmaf(xv[j], wb.y, l[5]);
        l[6] = fmaf(xv[j], wb.z, l[6]); l[7] = fmaf(xv[j], wb.w, l[7]);
    }
#pragma unroll
    for (int off = 16; off > 0; off >>= 1)
#pragma unroll
        for (int e = 0; e < EE; e++) l[e] += __shfl_xor_sync(0xFFFFFFFF, l[e], off);

    if (lane) return;
#pragma unroll
    for (int e = 0; e < EE; e++) l[e] += __ldg(br + e);
    float mx = l[0];
#pragma unroll
    for (int e = 1; e < EE; e++) mx = fmaxf(mx, l[e]);
    float s = 0.f, p[EE];
#pragma unroll
    for (int e = 0; e < EE; e++) { p[e] = __expf(l[e] - mx); s += p[e]; }
    float inv = 1.f / s;
#pragma unroll
    for (int e = 0; e < EE; e++) p[e] *= inv;

    float4* po = (float4*)(probs_out + (size_t)t * EE);
    po[0] = make_float4(p[0],p[1],p[2],p[3]);
    po[1] = make_float4(p[4],p[5],p[6],p[7]);

    int i0 = 0; float v0 = p[0];
#pragma unroll
    for (int e = 1; e < EE; e++) if (p[e] > v0) { v0 = p[e]; i0 = e; }
    int i1 = -1; float v1 = -1.f;
#pragma unroll
    for (int e = 0; e < EE; e++) if (e != i0 && p[e] > v1) { v1 = p[e]; i1 = e; }
    float rs = 1.f / (v0 + v1);

    int p0 = atomicAdd(&g_counts[i0], 1);
    g_tok[i0*TT+p0] = t; g_wt[i0*TT+p0] = v0*rs; g_slot[i0*TT+p0] = 2*t;
    int p1 = atomicAdd(&g_counts[i1], 1);
    g_tok[i1*TT+p1] = t; g_wt[i1*TT+p1] = v1*rs; g_slot[i1*TT+p1] = 2*t+1;
}

// ---------------- FFN: fp16 mma.sync, HC=64, reg-pipelined GEMM1 ------------
__global__ __launch_bounds__(256, 2) void ffn_kernel(
    const float* __restrict__ xg,
    const float* __restrict__ b1g, const float* __restrict__ b2g)
{
    extern __shared__ char sh[];
    __shared__ int toks[BM]; __shared__ float wts[BM]; __shared__ int slts[BM];

    int tid = threadIdx.x, wid = tid >> 5, lane = tid & 31;
    int qr = lane >> 2, qc = lane & 3;
    int wr = wid & 3, wc = wid >> 2;     // GEMM1: 4M x 2N (16x32 tile)
    int wr2 = wid & 1, wc2 = wid >> 1;   // GEMM2: 2M x 4N (32x64 tile)

    int e = -1, tile = 0, cnt = 0, acc = 0;
#pragma unroll
    for (int i = 0; i < EE; i++) {
        int c = g_counts[i], nt = (c + BM - 1) / BM;
        if (e < 0 && (int)blockIdx.x < acc + nt) { e = i; tile = blockIdx.x - acc; cnt = c; }
        acc += nt;
    }
    if (e < 0) return;
    int base = tile * BM, mval = min(BM, cnt - base);

    if (tid < BM) {
        if (tid < mval) {
            toks[tid] = g_tok [e*TT + base + tid];
            wts [tid] = g_wt  [e*TT + base + tid];
            slts[tid] = g_slot[e*TT + base + tid];
        } else { toks[tid] = 0; wts[tid] = 0.f; slts[tid] = 0; }
    }
    __syncthreads();

    const __half* w1te = g_w1t + (size_t)e * HH * DD;   // [H][D]
    const __half* w2te = g_w2t + (size_t)e * DD * HH;   // [D][H]
    const float*  b1e  = b1g + (size_t)e * HH;
    const float*  b2e  = b2g + (size_t)e * DD;

    uint32_t smb = s2u(sh);
    uint32_t xs_b = smb + XS_OFF, w1_b = smb + W1_OFF;
    uint32_t w2_b = smb + W2_OFF, hs_b = smb + HS_OFF;

    int a_row = lane & 15, a_kof = 8 * (lane >> 4);
    int b_row = ((lane >> 4) << 3) + (lane & 7);
    int b_kof = 8 * ((lane >> 3) & 1);

    // prologue: W1 chunk 0 (64 rows x 512B, swizzled)
#pragma unroll
    for (int i = 0; i < 8; i++) {
        int f = tid + i*256, row = f >> 5, seg = f & 31;
        cpa16(w1_b + (uint32_t)(row*512 + SWZ512(seg*16, row)),
              w1te + (size_t)row*DD + seg*8);
    }
    CP_COMMIT();
    for (int i4 = tid; i4 < BM*64; i4 += 256) {
        int r = i4 >> 6, c4 = i4 & 63;
        float4 v = (r < mval) ? __ldg((const float4*)(xg + (size_t)toks[r]*DD + c4*4))
                              : make_float4(0.f,0.f,0.f,0.f);
        __half2 h0 = __floats2half2_rn(v.x, v.y);
        __half2 h1 = __floats2half2_rn(v.z, v.w);
        uint2 u;
        u.x = *reinterpret_cast<uint32_t*>(&h0);
        u.y = *reinterpret_cast<uint32_t*>(&h1);
        *reinterpret_cast<uint2*>(sh + XS_OFF + r*512 + SWZ512(c4*8, r)) = u;
    }
    CP_WAIT0();
    __syncthreads();

    float c2[2][8][4];
#pragma unroll
    for (int mt = 0; mt < 2; mt++)
#pragma unroll
        for (int nt = 0; nt < 8; nt++)
#pragma unroll
            for (int c = 0; c < 4; c++) c2[mt][nt][c] = 0.f;

#pragma unroll 1
    for (int hc = 0; hc < NCH; hc++) {
        // prefetch W2 chunk hc (256 rows x 128B, stride 144B)
#pragma unroll
        for (int i = 0; i < 8; i++) {
            int f = tid + i*256, row = f >> 3, seg = f & 7;
            cpa16(w2_b + (uint32_t)(row*(W2_S*2) + seg*16),
                  w2te + (size_t)row*HH + hc*HC + seg*8);
        }
        CP_COMMIT();

        // ---- GEMM1 (register-pipelined): C1[64,64] = X @ W1c ; tile 16x32
        float c1[4][4];
#pragma unroll
        for (int nt = 0; nt < 4; nt++)
#pragma unroll
            for (int c = 0; c < 4; c++) c1[nt][c] = 0.f;

        {
            uint32_t af[2][4], b0f[2][4], b1f[2][4];
            {   // preload ks=0
                int row = wr*16 + a_row;
                ldsm4(af[0][0],af[0][1],af[0][2],af[0][3],
                      xs_b + (uint32_t)(row*512 + SWZ512((a_kof)*2, row)));
                row = wc*32 + b_row;
                ldsm4(b0f[0][0],b0f[0][1],b0f[0][2],b0f[0][3],
                      w1_b + (uint32_t)(row*512 + SWZ512((b_kof)*2, row)));
                row += 16;
                ldsm4(b1f[0][0],b1f[0][1],b1f[0][2],b1f[0][3],
                      w1_b + (uint32_t)(row*512 + SWZ512((b_kof)*2, row)));
            }
#pragma unroll
            for (int ks = 0; ks < 16; ks++) {
                int cur = ks & 1, nxt = cur ^ 1;
                if (ks < 15) {
                    int k0 = (ks + 1) * 16;
                    int row = wr*16 + a_row;
                    ldsm4(af[nxt][0],af[nxt][1],af[nxt][2],af[nxt][3],
                          xs_b + (uint32_t)(row*512 + SWZ512((k0 + a_kof)*2, row)));
                    row = wc*32 + b_row;
                    ldsm4(b0f[nxt][0],b0f[nxt][1],b0f[nxt][2],b0f[nxt][3],
                          w1_b + (uint32_t)(row*512 + SWZ512((k0 + b_kof)*2, row)));
                    row += 16;
                    ldsm4(b1f[nxt][0],b1f[nxt][1],b1f[nxt][2],b1f[nxt][3],
                          w1_b + (uint32_t)(row*512 + SWZ512((k0 + b_kof)*2, row)));
                }
                mma16(c1[0], af[cur], b0f[cur][0], b0f[cur][1]);
                mma16(c1[1], af[cur], b0f[cur][2], b0f[cur][3]);
                mma16(c1[2], af[cur], b1f[cur][0], b1f[cur][1]);
                mma16(c1[3], af[cur], b1f[cur][2], b1f[cur][3]);
            }
        }

        // ---- bias + fast GELU -> Hs (W2 cp.async still in flight)
#pragma unroll
        for (int nt = 0; nt < 4; nt++) {
            int col = wc*32 + nt*8 + 2*qc;
            float bb0 = __ldg(b1e + hc*HC + col);
            float bb1 = __ldg(b1e + hc*HC + col + 1);
            int r = wr*16 + qr;
            float v0 = gelu_f(c1[nt][0] + bb0), v1 = gelu_f(c1[nt][1] + bb1);
            float v2 = gelu_f(c1[nt][2] + bb0), v3 = gelu_f(c1[nt][3] + bb1);
            *reinterpret_cast<__half2*>(sh + HS_OFF + (r*HS_S + col)*2)
                = __floats2half2_rn(v0, v1);
            *reinterpret_cast<__half2*>(sh + HS_OFF + ((r+8)*HS_S + col)*2)
                = __floats2half2_rn(v2, v3);
        }
        CP_WAIT0();        // W2 chunk ready
        __syncthreads();   // Hs + W2 visible

        // prefetch W1 chunk hc+1 (overlaps GEMM2)
        if (hc + 1 < NCH) {
#pragma unroll
            for (int i = 0; i < 8; i++) {
                int f = tid + i*256, row = f >> 5, seg = f & 31;
                cpa16(w1_b + (uint32_t)(row*512 + SWZ512(seg*16, row)),
                      w1te + (size_t)((hc+1)*HC + row)*DD + seg*8);
            }
        }
        CP_COMMIT();

        // ---- GEMM2: C2[64,256] += H[64,64] @ W2c ; warp tile 32x64
#pragma unroll
        for (int ks = 0; ks < 4; ks++) {
            int k0 = ks * 16;
            uint32_t a0[4], a1[4];
            ldsm4(a0[0],a0[1],a0[2],a0[3],
                  hs_b + (uint32_t)(((wr2*32 + a_row)*HS_S + k0 + a_kof) * 2));
            ldsm4(a1[0],a1[1],a1[2],a1[3],
                  hs_b + (uint32_t)(((wr2*32 + 16 + a_row)*HS_S + k0 + a_kof) * 2));
#pragma unroll
            for (int p = 0; p < 4; p++) {
                uint32_t b[4];
                ldsm4(b[0],b[1],b[2],b[3],
                      w2_b + (uint32_t)(((wc2*64 + p*16 + b_row)*W2_S + k0 + b_kof) * 2));
                mma16(c2[0][2*p],   a0, b[0], b[1]);
                mma16(c2[0][2*p+1], a0, b[2], b[3]);
                mma16(c2[1][2*p],   a1, b[0], b[1]);
                mma16(c2[1][2*p+1], a1, b[2], b[3]);
            }
        }
        CP_WAIT0();    // W1 next ready
        __syncthreads();
    }

    // ---- epilogue: contrib[slot] = w * (y + b2)
#pragma unroll
    for (int mt = 0; mt < 2; mt++)
#pragma unroll
        for (int half = 0; half < 2; half++) {
            int r = wr2*32 + mt*16 + qr + half*8;
            if (r < mval) {
                float w = wts[r];
                float* crow = g_contrib + (size_t)slts[r] * DD;
#pragma unroll
                for (int nt = 0; nt < 8; nt++) {
                    int col = wc2*64 + nt*8 + 2*qc;
                    float2 o;
                    o.x = w * (c2[mt][nt][half*2+0] + __ldg(b2e + col));
                    o.y = w * (c2[mt][nt][half*2+1] + __ldg(b2e + col + 1));
                    *(float2*)(crow + col) = o;
                }
            }
        }
}

// ---------------- combine + counter reset -----------------------------------
__global__ __launch_bounds__(256) void combine_kernel(float* __restrict__ out)
{
    int g = blockIdx.x * 256 + threadIdx.x;
    int t = g >> 6, q = g & 63;
    const float4* c4 = (const float4*)g_contrib;
    float4 a = c4[(size_t)(2*t) * 64 + q];
    float4 b = c4[(size_t)(2*t+1) * 64 + q];
    ((float4*)out)[g] = make_float4(a.x+b.x, a.y+b.y, a.z+b.z, a.w+b.w);
    if (g < EE) g_counts[g] = 0;
}

extern "C" void kernel_launch(void* const* d_in, const int* in_sizes, int n_in,
                              void* d_out, int out_size)
{
    const float* x  = (const float*)d_in[0];
    const float* wr = (const float*)d_in[1];
    const float* br = (const float*)d_in[2];
    const float* w1 = (const float*)d_in[3];
    const float* b1 = (const float*)d_in[4];
    const float* w2 = (const float*)d_in[5];
    const float* b2 = (const float*)d_in[6];
    float* out = (float*)d_out;
    float* probs_out = out + (size_t)TT * DD;

    prep_kernel<<<6144, 256>>>(w1, w2, x, wr, br, probs_out);

    cudaFuncSetAttribute(ffn_kernel, cudaFuncAttributeMaxDynamicSharedMemorySize, SMEM_BYTES);
    ffn_kernel<<<(2*TT)/BM + EE, 256, SMEM_BYTES>>>(x, b1, b2);

    combine_kernel<<<(TT*DD/4)/256, 256>>>(out);
}

// round 15
// speedup vs baseline: 1.1319x; 1.0058x over previous
#include <cuda_runtime.h>
#include <cuda_fp16.h>
#include <cstdint>
#include <math.h>

#define TT 16384
#define DD 256
#define HH 1024
#define EE 8
#define BM 64
#define HC 64
#define NCH (HH/HC)   // 16

// smem byte offsets (dynamic smem base)
#define XS_OFF  0u
#define W1_OFF  32768u
#define W2_OFF  65536u
#define HS_OFF  102400u
#define W2_S 72
#define HS_S 72
#define SMEM_BYTES 111616

#define SWZ512(byte, row) ((byte) ^ (((row) & 7) << 4))

__device__ int    g_counts[EE];
__device__ int    g_tok [EE*TT];
__device__ float  g_wt  [EE*TT];
__device__ int    g_slot[EE*TT];
__device__ float  g_contrib[2*TT*DD];
__device__ __half g_w1t[EE*HH*DD];   // [E][H][D] fp16
__device__ __half g_w2t[EE*DD*HH];   // [E][D][H] fp16

__device__ __forceinline__ uint32_t s2u(const void* p) {
    uint32_t a;
    asm("{ .reg .u64 t; cvta.to.shared.u64 t, %1; cvt.u32.u64 %0, t; }" : "=r"(a) : "l"(p));
    return a;
}
__device__ __forceinline__ void cpa16(uint32_t s, const void* g) {
    asm volatile("cp.async.cg.shared.global [%0], [%1], 16;" :: "r"(s), "l"(g));
}
#define CP_COMMIT() asm volatile("cp.async.commit_group;")
#define CP_WAIT0()  asm volatile("cp.async.wait_group 0;")

__device__ __forceinline__ void ldsm4(uint32_t& r0, uint32_t& r1, uint32_t& r2,
                                      uint32_t& r3, uint32_t a) {
    asm volatile("ldmatrix.sync.aligned.m8n8.x4.shared.b16 {%0,%1,%2,%3}, [%4];"
                 : "=r"(r0), "=r"(r1), "=r"(r2), "=r"(r3) : "r"(a));
}
__device__ __forceinline__ void mma16(float* c, const uint32_t* a,
                                      uint32_t b0, uint32_t b1) {
    asm("mma.sync.aligned.m16n8k16.row.col.f32.f16.f16.f32 "
        "{%0,%1,%2,%3}, {%4,%5,%6,%7}, {%8,%9}, {%0,%1,%2,%3};"
        : "+f"(c[0]), "+f"(c[1]), "+f"(c[2]), "+f"(c[3])
        : "r"(a[0]), "r"(a[1]), "r"(a[2]), "r"(a[3]), "r"(b0), "r"(b1));
}
__device__ __forceinline__ float gelu_f(float v) {
    float u = 0.7978845608f * fmaf(0.044715f * v, v * v, v);
    float t;
    asm("tanh.approx.f32 %0, %1;" : "=f"(t) : "f"(u));
    return 0.5f * v * (1.f + t);
}

// ---- fused prep, fat blocks:
//   blocks 0..511  : weight transpose+cvt, 8 tiles each
//   blocks 512..767: router, 64 tokens each (warp = 8 tokens, batched x loads)
__global__ __launch_bounds__(256) void prep_kernel(
    const float* __restrict__ w1in, const float* __restrict__ w2in,
    const float* __restrict__ x,    const float* __restrict__ wrr,
    const float* __restrict__ br,   float* __restrict__ probs_out)
{
    __shared__ float tile[32][33];
    __shared__ float4 wsm[544];       // 512 float4 + pad/16 (conflict-free)
    int bid = blockIdx.x;
    int tid = threadIdx.x;

    if (bid < 512) {
        int c = tid & 31, r8 = tid >> 5;
#pragma unroll 1
        for (int sub = 0; sub < 8; sub++) {
            int ob = bid * 8 + sub;
            int which = ob >> 11;          // 0: w1 (256x1024), 1: w2 (1024x256)
            int rem = ob & 2047;
            int e = rem >> 8, b = rem & 255;
            const float* in = which ? w2in : w1in;
            __half* outp = which ? g_w2t : g_w1t;
            int M = which ? HH : DD;
            int N = which ? DD : HH;
            int ntj = N >> 5;
            int ti = b / ntj, tj = b % ntj;
            const float* ine = in + (size_t)e * M * N;
            __half* oute = outp + (size_t)e * M * N;
#pragma unroll
            for (int it = 0; it < 4; it++) {
                int r = it * 8 + r8;
                tile[r][c] = __ldg(ine + (size_t)(ti*32 + r) * N + tj*32 + c);
            }
            __syncthreads();
#pragma unroll
            for (int it = 0; it < 4; it++) {
                int r = it * 8 + r8;
                oute[(size_t)(tj*32 + r) * M + ti*32 + c] = __float2half_rn(tile[c][r]);
            }
            __syncthreads();
        }
        return;
    }

    // ---- router ----
#pragma unroll
    for (int i = tid; i < 512; i += 256)
        wsm[i + (i >> 4)] = __ldg(((const float4*)wrr) + i);
    __syncthreads();

    int lane = tid & 31, wid = tid >> 5;
    int t0 = (bid - 512) * 64 + wid * 8;

    // batch-load x for all 8 tokens (16 LDG.128 in flight -> DRAM-saturating)
    float4 xa[8][2];
#pragma unroll
    for (int i = 0; i < 8; i++) {
        const float4* xr = (const float4*)(x + (size_t)(t0 + i) * DD + lane * 8);
        xa[i][0] = __ldg(xr);
        xa[i][1] = __ldg(xr + 1);
    }

    const float4* wl = wsm + lane * 17;   // logical lane*16+k -> phys lane*17+k
#pragma unroll 1
    for (int i = 0; i < 8; i++) {
        int t = t0 + i;
        float xv[8] = {xa[i][0].x, xa[i][0].y, xa[i][0].z, xa[i][0].w,
                       xa[i][1].x, xa[i][1].y, xa[i][1].z, xa[i][1].w};
        float l[EE];
#pragma unroll
        for (int e = 0; e < EE; e++) l[e] = 0.f;
#pragma unroll
        for (int j = 0; j < 8; j++) {
            float4 wa = wl[2*j], wb = wl[2*j + 1];
            l[0] = fmaf(xv[j], wa.x, l[0]); l[1] = fmaf(xv[j], wa.y, l[1]);
            l[2] = fmaf(xv[j], wa.z, l[2]); l[3] = fmaf(xv[j], wa.w, l[3]);
            l[4] = fmaf(xv[j], wb.x, l[4]); l[5] = fmaf(xv[j], wb.y, l[5]);
            l[6] = fmaf(xv[j], wb.z, l[6]); l[7] = fmaf(xv[j], wb.w, l[7]);
        }
#pragma unroll
        for (int off = 16; off > 0; off >>= 1)
#pragma unroll
            for (int e = 0; e < EE; e++) l[e] += __shfl_xor_sync(0xFFFFFFFF, l[e], off);

        if (lane == 0) {
#pragma unroll
            for (int e = 0; e < EE; e++) l[e] += __ldg(br + e);
            float mx = l[0];
#pragma unroll
            for (int e = 1; e < EE; e++) mx = fmaxf(mx, l[e]);
            float s = 0.f, p[EE];
#pragma unroll
            for (int e = 0; e < EE; e++) { p[e] = __expf(l[e] - mx); s += p[e]; }
            float inv = 1.f / s;
#pragma unroll
            for (int e = 0; e < EE; e++) p[e] *= inv;

            float4* po = (float4*)(probs_out + (size_t)t * EE);
            po[0] = make_float4(p[0],p[1],p[2],p[3]);
            po[1] = make_float4(p[4],p[5],p[6],p[7]);

            int i0 = 0; float v0 = p[0];
#pragma unroll
            for (int e = 1; e < EE; e++) if (p[e] > v0) { v0 = p[e]; i0 = e; }
            int i1 = -1; float v1 = -1.f;
#pragma unroll
            for (int e = 0; e < EE; e++) if (e != i0 && p[e] > v1) { v1 = p[e]; i1 = e; }
            float rs = 1.f / (v0 + v1);

            int p0 = atomicAdd(&g_counts[i0], 1);
            g_tok[i0*TT+p0] = t; g_wt[i0*TT+p0] = v0*rs; g_slot[i0*TT+p0] = 2*t;
            int p1 = atomicAdd(&g_counts[i1], 1);
            g_tok[i1*TT+p1] = t; g_wt[i1*TT+p1] = v1*rs; g_slot[i1*TT+p1] = 2*t+1;
        }
    }
}

// ---------------- FFN: fp16 mma.sync, HC=64, reg-pipelined GEMM1 ------------
__global__ __launch_bounds__(256, 2) void ffn_kernel(
    const float* __restrict__ xg,
    const float* __restrict__ b1g, const float* __restrict__ b2g)
{
    extern __shared__ char sh[];
    __shared__ int toks[BM]; __shared__ float wts[BM]; __shared__ int slts[BM];

    int tid = threadIdx.x, wid = tid >> 5, lane = tid & 31;
    int qr = lane >> 2, qc = lane & 3;
    int wr = wid & 3, wc = wid >> 2;     // GEMM1: 4M x 2N (16x32 tile)
    int wr2 = wid & 1, wc2 = wid >> 1;   // GEMM2: 2M x 4N (32x64 tile)

    int e = -1, tile = 0, cnt = 0, acc = 0;
#pragma unroll
    for (int i = 0; i < EE; i++) {
        int c = g_counts[i], nt = (c + BM - 1) / BM;
        if (e < 0 && (int)blockIdx.x < acc + nt) { e = i; tile = blockIdx.x - acc; cnt = c; }
        acc += nt;
    }
    if (e < 0) return;
    int base = tile * BM, mval = min(BM, cnt - base);

    if (tid < BM) {
        if (tid < mval) {
            toks[tid] = g_tok [e*TT + base + tid];
            wts [tid] = g_wt  [e*TT + base + tid];
            slts[tid] = g_slot[e*TT + base + tid];
        } else { toks[tid] = 0; wts[tid] = 0.f; slts[tid] = 0; }
    }
    __syncthreads();

    const __half* w1te = g_w1t + (size_t)e * HH * DD;   // [H][D]
    const __half* w2te = g_w2t + (size_t)e * DD * HH;   // [D][H]
    const float*  b1e  = b1g + (size_t)e * HH;
    const float*  b2e  = b2g + (size_t)e * DD;

    uint32_t smb = s2u(sh);
    uint32_t xs_b = smb + XS_OFF, w1_b = smb + W1_OFF;
    uint32_t w2_b = smb + W2_OFF, hs_b = smb + HS_OFF;

    int a_row = lane & 15, a_kof = 8 * (lane >> 4);
    int b_row = ((lane >> 4) << 3) + (lane & 7);
    int b_kof = 8 * ((lane >> 3) & 1);

    // prologue: W1 chunk 0 (64 rows x 512B, swizzled)
#pragma unroll
    for (int i = 0; i < 8; i++) {
        int f = tid + i*256, row = f >> 5, seg = f & 31;
        cpa16(w1_b + (uint32_t)(row*512 + SWZ512(seg*16, row)),
              w1te + (size_t)row*DD + seg*8);
    }
    CP_COMMIT();
    for (int i4 = tid; i4 < BM*64; i4 += 256) {
        int r = i4 >> 6, c4 = i4 & 63;
        float4 v = (r < mval) ? __ldg((const float4*)(xg + (size_t)toks[r]*DD + c4*4))
                              : make_float4(0.f,0.f,0.f,0.f);
        __half2 h0 = __floats2half2_rn(v.x, v.y);
        __half2 h1 = __floats2half2_rn(v.z, v.w);
        uint2 u;
        u.x = *reinterpret_cast<uint32_t*>(&h0);
        u.y = *reinterpret_cast<uint32_t*>(&h1);
        *reinterpret_cast<uint2*>(sh + XS_OFF + r*512 + SWZ512(c4*8, r)) = u;
    }
    CP_WAIT0();
    __syncthreads();

    float c2[2][8][4];
#pragma unroll
    for (int mt = 0; mt < 2; mt++)
#pragma unroll
        for (int nt = 0; nt < 8; nt++)
#pragma unroll
            for (int c = 0; c < 4; c++) c2[mt][nt][c] = 0.f;

#pragma unroll 1
    for (int hc = 0; hc < NCH; hc++) {
#pragma unroll
        for (int i = 0; i < 8; i++) {
            int f = tid + i*256, row = f >> 3, seg = f & 7;
            cpa16(w2_b + (uint32_t)(row*(W2_S*2) + seg*16),
                  w2te + (size_t)row*HH + hc*HC + seg*8);
        }
        CP_COMMIT();

        float c1[4][4];
#pragma unroll
        for (int nt = 0; nt < 4; nt++)
#pragma unroll
            for (int c = 0; c < 4; c++) c1[nt][c] = 0.f;

        {
            uint32_t af[2][4], b0f[2][4], b1f[2][4];
            {
                int row = wr*16 + a_row;
                ldsm4(af[0][0],af[0][1],af[0][2],af[0][3],
                      xs_b + (uint32_t)(row*512 + SWZ512((a_kof)*2, row)));
                row = wc*32 + b_row;
                ldsm4(b0f[0][0],b0f[0][1],b0f[0][2],b0f[0][3],
                      w1_b + (uint32_t)(row*512 + SWZ512((b_kof)*2, row)));
                row += 16;
                ldsm4(b1f[0][0],b1f[0][1],b1f[0][2],b1f[0][3],
                      w1_b + (uint32_t)(row*512 + SWZ512((b_kof)*2, row)));
            }
#pragma unroll
            for (int ks = 0; ks < 16; ks++) {
                int cur = ks & 1, nxt = cur ^ 1;
                if (ks < 15) {
                    int k0 = (ks + 1) * 16;
                    int row = wr*16 + a_row;
                    ldsm4(af[nxt][0],af[nxt][1],af[nxt][2],af[nxt][3],
                          xs_b + (uint32_t)(row*512 + SWZ512((k0 + a_kof)*2, row)));
                    row = wc*32 + b_row;
                    ldsm4(b0f[nxt][0],b0f[nxt][1],b0f[nxt][2],b0f[nxt][3],
                          w1_b + (uint32_t)(row*512 + SWZ512((k0 + b_kof)*2, row)));
                    row += 16;
                    ldsm4(b1f[nxt][0],b1f[nxt][1],b1f[nxt][2],b1f[nxt][3],
                          w1_b + (uint32_t)(row*512 + SWZ512((k0 + b_kof)*2, row)));
                }
                mma16(c1[0], af[cur], b0f[cur][0], b0f[cur][1]);
                mma16(c1[1], af[cur], b0f[cur][2], b0f[cur][3]);
                mma16(c1[2], af[cur], b1f[cur][0], b1f[cur][1]);
                mma16(c1[3], af[cur], b1f[cur][2], b1f[cur][3]);
            }
        }

#pragma unroll
        for (int nt = 0; nt < 4; nt++) {
            int col = wc*32 + nt*8 + 2*qc;
            float bb0 = __ldg(b1e + hc*HC + col);
            float bb1 = __ldg(b1e + hc*HC + col + 1);
            int r = wr*16 + qr;
            float v0 = gelu_f(c1[nt][0] + bb0), v1 = gelu_f(c1[nt][1] + bb1);
            float v2 = gelu_f(c1[nt][2] + bb0), v3 = gelu_f(c1[nt][3] + bb1);
            *reinterpret_cast<__half2*>(sh + HS_OFF + (r*HS_S + col)*2)
                = __floats2half2_rn(v0, v1);
            *reinterpret_cast<__half2*>(sh + HS_OFF + ((r+8)*HS_S + col)*2)
                = __floats2half2_rn(v2, v3);
        }
        CP_WAIT0();
        __syncthreads();

        if (hc + 1 < NCH) {
#pragma unroll
            for (int i = 0; i < 8; i++) {
                int f = tid + i*256, row = f >> 5, seg = f & 31;
                cpa16(w1_b + (uint32_t)(row*512 + SWZ512(seg*16, row)),
                      w1te + (size_t)((hc+1)*HC + row)*DD + seg*8);
            }
        }
        CP_COMMIT();

#pragma unroll
        for (int ks = 0; ks < 4; ks++) {
            int k0 = ks * 16;
            uint32_t a0[4], a1[4];
            ldsm4(a0[0],a0[1],a0[2],a0[3],
                  hs_b + (uint32_t)(((wr2*32 + a_row)*HS_S + k0 + a_kof) * 2));
            ldsm4(a1[0],a1[1],a1[2],a1[3],
                  hs_b + (uint32_t)(((wr2*32 + 16 + a_row)*HS_S + k0 + a_kof) * 2));
#pragma unroll
            for (int p = 0; p < 4; p++) {
                uint32_t b[4];
                ldsm4(b[0],b[1],b[2],b[3],
                      w2_b + (uint32_t)(((wc2*64 + p*16 + b_row)*W2_S + k0 + b_kof) * 2));
                mma16(c2[0][2*p],   a0, b[0], b[1]);
                mma16(c2[0][2*p+1], a0, b[2], b[3]);
                mma16(c2[1][2*p],   a1, b[0], b[1]);
                mma16(c2[1][2*p+1], a1, b[2], b[3]);
            }
        }
        CP_WAIT0();
        __syncthreads();
    }

    // ---- epilogue: contrib[slot] = w * (y + b2)
#pragma unroll
    for (int mt = 0; mt < 2; mt++)
#pragma unroll
        for (int half = 0; half < 2; half++) {
            int r = wr2*32 + mt*16 + qr + half*8;
            if (r < mval) {
                float w = wts[r];
                float* crow = g_contrib + (size_t)slts[r] * DD;
#pragma unroll
                for (int nt = 0; nt < 8; nt++) {
                    int col = wc2*64 + nt*8 + 2*qc;
                    float2 o;
                    o.x = w * (c2[mt][nt][half*2+0] + __ldg(b2e + col));
                    o.y = w * (c2[mt][nt][half*2+1] + __ldg(b2e + col + 1));
                    *(float2*)(crow + col) = o;
                }
            }
        }
}

// ---------------- combine + counter reset -----------------------------------
__global__ __launch_bounds__(256) void combine_kernel(float* __restrict__ out)
{
    int g = blockIdx.x * 256 + threadIdx.x;
    int t = g >> 6, q = g & 63;
    const float4* c4 = (const float4*)g_contrib;
    float4 a = c4[(size_t)(2*t) * 64 + q];
    float4 b = c4[(size_t)(2*t+1) * 64 + q];
    ((float4*)out)[g] = make_float4(a.x+b.x, a.y+b.y, a.z+b.z, a.w+b.w);
    if (g < EE) g_counts[g] = 0;
}

extern "C" void kernel_launch(void* const* d_in, const int* in_sizes, int n_in,
                              void* d_out, int out_size)
{
    const float* x  = (const float*)d_in[0];
    const float* wr = (const float*)d_in[1];
    const float* br = (const float*)d_in[2];
    const float* w1 = (const float*)d_in[3];
    const float* b1 = (const float*)d_in[4];
    const float* w2 = (const float*)d_in[5];
    const float* b2 = (const float*)d_in[6];
    float* out = (float*)d_out;
    float* probs_out = out + (size_t)TT * DD;

    prep_kernel<<<768, 256>>>(w1, w2, x, wr, br, probs_out);

    cudaFuncSetAttribute(ffn_kernel, cudaFuncAttributeMaxDynamicSharedMemorySize, SMEM_BYTES);
    ffn_kernel<<<(2*TT)/BM + EE, 256, SMEM_BYTES>>>(x, b1, b2);

    combine_kernel<<<(TT*DD/4)/256, 256>>>(out);
}

// round 16
// speedup vs baseline: 1.2330x; 1.0893x over previous
#include <cuda_runtime.h>
#include <cuda_fp16.h>
#include <cstdint>
#include <math.h>

#define TT 16384
#define DD 256
#define HH 1024
#define EE 8
#define BM 64
#define HC 64
#define NCH (HH/HC)   // 16

// smem byte offsets
#define XS_OFF  0u        // X:   64 rows x 512B, SWZ512
#define W1_OFF  32768u    // W1c: 256 d-rows x 128B, SWZ128  ([k=d][n=h])
#define W2_OFF  65536u    // W2c: 64 h-rows x 512B, SWZ512   ([k=h][n=d])
#define HS_OFF  98304u    // Hs:  64 rows x 144B (stride 72 halves)
#define HS_S 72
#define SMEM_BYTES 107520

#define SWZ512(byte, row) ((byte) ^ (((row) & 7) << 4))
#define SWZ128(byte, row) ((byte) ^ (((row) & 7) << 4))

__device__ int    g_counts[EE];
__device__ int    g_tok [EE*TT];
__device__ float  g_wt  [EE*TT];
__device__ int    g_slot[EE*TT];
__device__ float  g_contrib[2*TT*DD];
__device__ __half g_w1h[EE*DD*HH];   // [E][D][H] fp16 (original layout)
__device__ __half g_w2h[EE*HH*DD];   // [E][H][D] fp16 (original layout)

__device__ __forceinline__ uint32_t s2u(const void* p) {
    uint32_t a;
    asm("{ .reg .u64 t; cvta.to.shared.u64 t, %1; cvt.u32.u64 %0, t; }" : "=r"(a) : "l"(p));
    return a;
}
__device__ __forceinline__ void cpa16(uint32_t s, const void* g) {
    asm volatile("cp.async.cg.shared.global [%0], [%1], 16;" :: "r"(s), "l"(g));
}
#define CP_COMMIT() asm volatile("cp.async.commit_group;")
#define CP_WAIT0()  asm volatile("cp.async.wait_group 0;")

__device__ __forceinline__ void ldsm4(uint32_t& r0, uint32_t& r1, uint32_t& r2,
                                      uint32_t& r3, uint32_t a) {
    asm volatile("ldmatrix.sync.aligned.m8n8.x4.shared.b16 {%0,%1,%2,%3}, [%4];"
                 : "=r"(r0), "=r"(r1), "=r"(r2), "=r"(r3) : "r"(a));
}
__device__ __forceinline__ void ldsm4t(uint32_t& r0, uint32_t& r1, uint32_t& r2,
                                       uint32_t& r3, uint32_t a) {
    asm volatile("ldmatrix.sync.aligned.m8n8.x4.trans.shared.b16 {%0,%1,%2,%3}, [%4];"
                 : "=r"(r0), "=r"(r1), "=r"(r2), "=r"(r3) : "r"(a));
}
__device__ __forceinline__ void mma16(float* c, const uint32_t* a,
                                      uint32_t b0, uint32_t b1) {
    asm("mma.sync.aligned.m16n8k16.row.col.f32.f16.f16.f32 "
        "{%0,%1,%2,%3}, {%4,%5,%6,%7}, {%8,%9}, {%0,%1,%2,%3};"
        : "+f"(c[0]), "+f"(c[1]), "+f"(c[2]), "+f"(c[3])
        : "r"(a[0]), "r"(a[1]), "r"(a[2]), "r"(a[3]), "r"(b0), "r"(b1));
}
__device__ __forceinline__ float gelu_f(float v) {
    float u = 0.7978845608f * fmaf(0.044715f * v, v * v, v);
    float t;
    asm("tanh.approx.f32 %0, %1;" : "=f"(t) : "f"(u));
    return 0.5f * v * (1.f + t);
}

// ---- fused prep: streaming fp16 convert (blocks 0..2047) + router (2048..4095)
__global__ __launch_bounds__(256) void prep_kernel(
    const float* __restrict__ w1in, const float* __restrict__ w2in,
    const float* __restrict__ x,    const float* __restrict__ wrr,
    const float* __restrict__ br,   float* __restrict__ probs_out)
{
    __shared__ float4 wsm[544];       // 512 float4 + pad/16 (conflict-free)
    int bid = blockIdx.x;
    int tid = threadIdx.x;

    if (bid < 2048) {
        // elementwise convert, same layout: 524288 float4 per weight
        int i = bid * 256 + tid;
        float4 a = __ldg((const float4*)w1in + i);
        float4 b = __ldg((const float4*)w2in + i);
        __half2 a0 = __floats2half2_rn(a.x, a.y), a1 = __floats2half2_rn(a.z, a.w);
        __half2 b0 = __floats2half2_rn(b.x, b.y), b1 = __floats2half2_rn(b.z, b.w);
        uint2 ua, ub;
        ua.x = *reinterpret_cast<uint32_t*>(&a0); ua.y = *reinterpret_cast<uint32_t*>(&a1);
        ub.x = *reinterpret_cast<uint32_t*>(&b0); ub.y = *reinterpret_cast<uint32_t*>(&b1);
        ((uint2*)g_w1h)[i] = ua;
        ((uint2*)g_w2h)[i] = ub;
        return;
    }

    // ---- router: warp per token, w_router staged in padded smem ----
#pragma unroll
    for (int i = tid; i < 512; i += 256)
        wsm[i + (i >> 4)] = __ldg(((const float4*)wrr) + i);
    __syncthreads();

    int lane = tid & 31;
    int t = ((bid - 2048) * 256 + tid) >> 5;
    if (t >= TT) return;

    const float4* xr = (const float4*)(x + (size_t)t * DD + lane * 8);
    float4 x0 = __ldg(xr), x1 = __ldg(xr + 1);
    float xv[8] = {x0.x,x0.y,x0.z,x0.w,x1.x,x1.y,x1.z,x1.w};

    float l[EE];
#pragma unroll
    for (int e = 0; e < EE; e++) l[e] = 0.f;
    const float4* wl = wsm + lane * 17;
#pragma unroll
    for (int j = 0; j < 8; j++) {
        float4 wa = wl[2*j], wb = wl[2*j + 1];
        l[0] = fmaf(xv[j], wa.x, l[0]); l[1] = fmaf(xv[j], wa.y, l[1]);
        l[2] = fmaf(xv[j], wa.z, l[2]); l[3] = fmaf(xv[j], wa.w, l[3]);
        l[4] = fmaf(xv[j], wb.x, l[4]); l[5] = fmaf(xv[j], wb.y, l[5]);
        l[6] = fmaf(xv[j], wb.z, l[6]); l[7] = fmaf(xv[j], wb.w, l[7]);
    }
#pragma unroll
    for (int off = 16; off > 0; off >>= 1)
#pragma unroll
        for (int e = 0; e < EE; e++) l[e] += __shfl_xor_sync(0xFFFFFFFF, l[e], off);

    if (lane) return;
#pragma unroll
    for (int e = 0; e < EE; e++) l[e] += __ldg(br + e);
    float mx = l[0];
#pragma unroll
    for (int e = 1; e < EE; e++) mx = fmaxf(mx, l[e]);
    float s = 0.f, p[EE];
#pragma unroll
    for (int e = 0; e < EE; e++) { p[e] = __expf(l[e] - mx); s += p[e]; }
    float inv = 1.f / s;
#pragma unroll
    for (int e = 0; e < EE; e++) p[e] *= inv;

    float4* po = (float4*)(probs_out + (size_t)t * EE);
    po[0] = make_float4(p[0],p[1],p[2],p[3]);
    po[1] = make_float4(p[4],p[5],p[6],p[7]);

    int i0 = 0; float v0 = p[0];
#pragma unroll
    for (int e = 1; e < EE; e++) if (p[e] > v0) { v0 = p[e]; i0 = e; }
    int i1 = -1; float v1 = -1.f;
#pragma unroll
    for (int e = 0; e < EE; e++) if (e != i0 && p[e] > v1) { v1 = p[e]; i1 = e; }
    float rs = 1.f / (v0 + v1);

    int p0 = atomicAdd(&g_counts[i0], 1);
    g_tok[i0*TT+p0] = t; g_wt[i0*TT+p0] = v0*rs; g_slot[i0*TT+p0] = 2*t;
    int p1 = atomicAdd(&g_counts[i1], 1);
    g_tok[i1*TT+p1] = t; g_wt[i1*TT+p1] = v1*rs; g_slot[i1*TT+p1] = 2*t+1;
}

// ---------------- FFN: fp16 mma.sync + ldmatrix.trans B (no transpose) ------
__global__ __launch_bounds__(256, 2) void ffn_kernel(
    const float* __restrict__ xg,
    const float* __restrict__ b1g, const float* __restrict__ b2g)
{
    extern __shared__ char sh[];
    __shared__ int toks[BM]; __shared__ float wts[BM]; __shared__ int slts[BM];

    int tid = threadIdx.x, wid = tid >> 5, lane = tid & 31;
    int qr = lane >> 2, qc = lane & 3;
    int wr = wid & 3, wc = wid >> 2;     // GEMM1: 4M x 2N (16x32 tile)
    int wr2 = wid & 1, wc2 = wid >> 1;   // GEMM2: 2M x 4N (32x64 tile)

    int e = -1, tile = 0, cnt = 0, acc = 0;
#pragma unroll
    for (int i = 0; i < EE; i++) {
        int c = g_counts[i], nt = (c + BM - 1) / BM;
        if (e < 0 && (int)blockIdx.x < acc + nt) { e = i; tile = blockIdx.x - acc; cnt = c; }
        acc += nt;
    }
    if (e < 0) return;
    int base = tile * BM, mval = min(BM, cnt - base);

    if (tid < BM) {
        if (tid < mval) {
            toks[tid] = g_tok [e*TT + base + tid];
            wts [tid] = g_wt  [e*TT + base + tid];
            slts[tid] = g_slot[e*TT + base + tid];
        } else { toks[tid] = 0; wts[tid] = 0.f; slts[tid] = 0; }
    }
    __syncthreads();

    const __half* w1he = g_w1h + (size_t)e * DD * HH;   // [D][H]
    const __half* w2he = g_w2h + (size_t)e * HH * DD;   // [H][D]
    const float*  b1e  = b1g + (size_t)e * HH;
    const float*  b2e  = b2g + (size_t)e * DD;

    uint32_t smb = s2u(sh);
    uint32_t xs_b = smb + XS_OFF, w1_b = smb + W1_OFF;
    uint32_t w2_b = smb + W2_OFF, hs_b = smb + HS_OFF;

    int a_row = lane & 15, a_kof = 8 * (lane >> 4);
    // trans-B lane components: rows = k, col groups = n
    int bt_row = ((lane >> 3) & 1) * 8 + (lane & 7);   // k within 16
    int bt_cb  = (lane >> 4) * 16;                      // n byte offset within 32B

    // W1 chunk loader: 256 d-rows x 128B (cols h = hc*HC..+64), SWZ128
#define LD_W1(chunk) do {                                                      \
    _Pragma("unroll")                                                          \
    for (int i = 0; i < 8; i++) {                                              \
        int f = tid + i*256, row = f >> 3, seg = f & 7;                        \
        cpa16(w1_b + (uint32_t)(row*128 + SWZ128(seg*16, row)),                \
              w1he + (size_t)row*HH + (chunk)*HC + seg*8);                     \
    } } while(0)
    // W2 chunk loader: 64 h-rows x 512B (all d), SWZ512
#define LD_W2(chunk) do {                                                      \
    _Pragma("unroll")                                                          \
    for (int i = 0; i < 8; i++) {                                              \
        int f = tid + i*256, row = f >> 5, seg = f & 31;                       \
        cpa16(w2_b + (uint32_t)(row*512 + SWZ512(seg*16, row)),                \
              w2he + (size_t)((chunk)*HC + row)*DD + seg*8);                   \
    } } while(0)

    // prologue: W1 chunk 0 + gather X
    LD_W1(0);
    CP_COMMIT();
    for (int i4 = tid; i4 < BM*64; i4 += 256) {
        int r = i4 >> 6, c4 = i4 & 63;
        float4 v = (r < mval) ? __ldg((const float4*)(xg + (size_t)toks[r]*DD + c4*4))
                              : make_float4(0.f,0.f,0.f,0.f);
        __half2 h0 = __floats2half2_rn(v.x, v.y);
        __half2 h1 = __floats2half2_rn(v.z, v.w);
        uint2 u;
        u.x = *reinterpret_cast<uint32_t*>(&h0);
        u.y = *reinterpret_cast<uint32_t*>(&h1);
        *reinterpret_cast<uint2*>(sh + XS_OFF + r*512 + SWZ512(c4*8, r)) = u;
    }
    CP_WAIT0();
    __syncthreads();

    float c2[2][8][4];
#pragma unroll
    for (int mt = 0; mt < 2; mt++)
#pragma unroll
        for (int nt = 0; nt < 8; nt++)
#pragma unroll
            for (int c = 0; c < 4; c++) c2[mt][nt][c] = 0.f;

#pragma unroll 1
    for (int hc = 0; hc < NCH; hc++) {
        LD_W2(hc);
        CP_COMMIT();

        // ---- GEMM1 (reg-pipelined): C1[64,64] = X @ W1c ; warp tile 16x32
        float c1[4][4];
#pragma unroll
        for (int nt = 0; nt < 4; nt++)
#pragma unroll
            for (int c = 0; c < 4; c++) c1[nt][c] = 0.f;

        {
            uint32_t af[2][4], b0f[2][4], b1f[2][4];
            int byte0 = wc*64 + bt_cb;        // n group 0 (16 cols)
            int byte1 = byte0 + 32;           // n group 1
            {   // preload ks=0
                int row = wr*16 + a_row;
                ldsm4(af[0][0],af[0][1],af[0][2],af[0][3],
                      xs_b + (uint32_t)(row*512 + SWZ512((a_kof)*2, row)));
                int rk = bt_row;
                ldsm4t(b0f[0][0],b0f[0][1],b0f[0][2],b0f[0][3],
                       w1_b + (uint32_t)(rk*128 + SWZ128(byte0, rk)));
                ldsm4t(b1f[0][0],b1f[0][1],b1f[0][2],b1f[0][3],
                       w1_b + (uint32_t)(rk*128 + SWZ128(byte1, rk)));
            }
#pragma unroll
            for (int ks = 0; ks < 16; ks++) {
                int cur = ks & 1, nxt = cur ^ 1;
                if (ks < 15) {
                    int k0 = (ks + 1) * 16;
                    int row = wr*16 + a_row;
                    ldsm4(af[nxt][0],af[nxt][1],af[nxt][2],af[nxt][3],
                          xs_b + (uint32_t)(row*512 + SWZ512((k0 + a_kof)*2, row)));
                    int rk = k0 + bt_row;
                    ldsm4t(b0f[nxt][0],b0f[nxt][1],b0f[nxt][2],b0f[nxt][3],
                           w1_b + (uint32_t)(rk*128 + SWZ128(byte0, rk)));
                    ldsm4t(b1f[nxt][0],b1f[nxt][1],b1f[nxt][2],b1f[nxt][3],
                           w1_b + (uint32_t)(rk*128 + SWZ128(byte1, rk)));
                }
                mma16(c1[0], af[cur], b0f[cur][0], b0f[cur][1]);
                mma16(c1[1], af[cur], b0f[cur][2], b0f[cur][3]);
                mma16(c1[2], af[cur], b1f[cur][0], b1f[cur][1]);
                mma16(c1[3], af[cur], b1f[cur][2], b1f[cur][3]);
            }
        }

        // ---- bias + fast GELU -> Hs (W2 cp.async in flight)
#pragma unroll
        for (int nt = 0; nt < 4; nt++) {
            int col = wc*32 + nt*8 + 2*qc;
            float bb0 = __ldg(b1e + hc*HC + col);
            float bb1 = __ldg(b1e + hc*HC + col + 1);
            int r = wr*16 + qr;
            float v0 = gelu_f(c1[nt][0] + bb0), v1 = gelu_f(c1[nt][1] + bb1);
            float v2 = gelu_f(c1[nt][2] + bb0), v3 = gelu_f(c1[nt][3] + bb1);
            *reinterpret_cast<__half2*>(sh + HS_OFF + (r*HS_S + col)*2)
                = __floats2half2_rn(v0, v1);
            *reinterpret_cast<__half2*>(sh + HS_OFF + ((r+8)*HS_S + col)*2)
                = __floats2half2_rn(v2, v3);
        }
        CP_WAIT0();
        __syncthreads();   // Hs + W2 visible

        if (hc + 1 < NCH) LD_W1(hc + 1);   // overlaps GEMM2
        CP_COMMIT();

        // ---- GEMM2: C2[64,256] += H[64,64] @ W2c ; warp tile 32x64
#pragma unroll
        for (int ks = 0; ks < 4; ks++) {
            int k0 = ks * 16;
            uint32_t a0[4], a1[4];
            ldsm4(a0[0],a0[1],a0[2],a0[3],
                  hs_b + (uint32_t)(((wr2*32 + a_row)*HS_S + k0 + a_kof) * 2));
            ldsm4(a1[0],a1[1],a1[2],a1[3],
                  hs_b + (uint32_t)(((wr2*32 + 16 + a_row)*HS_S + k0 + a_kof) * 2));
            int rk = k0 + bt_row;              // h-row within chunk (0..63)
#pragma unroll
            for (int p = 0; p < 4; p++) {
                uint32_t b[4];
                int byte = wc2*128 + p*32 + bt_cb;
                ldsm4t(b[0],b[1],b[2],b[3],
                       w2_b + (uint32_t)(rk*512 + SWZ512(byte, rk)));
                mma16(c2[0][2*p],   a0, b[0], b[1]);
                mma16(c2[0][2*p+1], a0, b[2], b[3]);
                mma16(c2[1][2*p],   a1, b[0], b[1]);
                mma16(c2[1][2*p+1], a1, b[2], b[3]);
            }
        }
        CP_WAIT0();
        __syncthreads();
    }

    // ---- epilogue: contrib[slot] = w * (y + b2)
#pragma unroll
    for (int mt = 0; mt < 2; mt++)
#pragma unroll
        for (int half = 0; half < 2; half++) {
            int r = wr2*32 + mt*16 + qr + half*8;
            if (r < mval) {
                float w = wts[r];
                float* crow = g_contrib + (size_t)slts[r] * DD;
#pragma unroll
                for (int nt = 0; nt < 8; nt++) {
                    int col = wc2*64 + nt*8 + 2*qc;
                    float2 o;
                    o.x = w * (c2[mt][nt][half*2+0] + __ldg(b2e + col));
                    o.y = w * (c2[mt][nt][half*2+1] + __ldg(b2e + col + 1));
                    *(float2*)(crow + col) = o;
                }
            }
        }
}

// ---------------- combine + counter reset -----------------------------------
__global__ __launch_bounds__(256) void combine_kernel(float* __restrict__ out)
{
    int g = blockIdx.x * 256 + threadIdx.x;
    int t = g >> 6, q = g & 63;
    const float4* c4 = (const float4*)g_contrib;
    float4 a = c4[(size_t)(2*t) * 64 + q];
    float4 b = c4[(size_t)(2*t+1) * 64 + q];
    ((float4*)out)[g] = make_float4(a.x+b.x, a.y+b.y, a.z+b.z, a.w+b.w);
    if (g < EE) g_counts[g] = 0;
}

extern "C" void kernel_launch(void* const* d_in, const int* in_sizes, int n_in,
                              void* d_out, int out_size)
{
    const float* x  = (const float*)d_in[0];
    const float* wr = (const float*)d_in[1];
    const float* br = (const float*)d_in[2];
    const float* w1 = (const float*)d_in[3];
    const float* b1 = (const float*)d_in[4];
    const float* w2 = (const float*)d_in[5];
    const float* b2 = (const float*)d_in[6];
    float* out = (float*)d_out;
    float* probs_out = out + (size_t)TT * DD;

    prep_kernel<<<4096, 256>>>(w1, w2, x, wr, br, probs_out);

    cudaFuncSetAttribute(ffn_kernel, cudaFuncAttributeMaxDynamicSharedMemorySize, SMEM_BYTES);
    ffn_kernel<<<(2*TT)/BM + EE, 256, SMEM_BYTES>>>(x, b1, b2);

    combine_kernel<<<(TT*DD/4)/256, 256>>>(out);
}